// round 1
// baseline (speedup 1.0000x reference)
#include <cuda_runtime.h>
#include <cuda_bf16.h>

// Matcher: final_cost = -2 * gious  (class_mat in reference is dead code).
// Per batch b: Hungarian (Jonker-Volgenant) on cost[g][q] = -2*gious[b,q,g],
// rows g in [0, nactual_gt[b]), cols q in [0, 256).
// Outputs (concatenated float32):
//   out[0      .. B*Q)  = per_prop_gt_inds  (0 default, g for matched col)
//   out[B*Q .. 2*B*Q)   = proposal_matched_mask (1.0 for matched col)

#define BB 64
#define QQ 256
#define GG 64
#define CPAD 257   // padded cost row stride (floats) for conflict-free staging

__global__ void __launch_bounds__(32, 1) matcher_lsa_kernel(
    const float* __restrict__ gious,   // [B, Q, G] float32
    const int*   __restrict__ nactRaw, // int32 view of nactual_gt (int32 or int64)
    float*       __restrict__ out)     // [2*B*Q] float32
{
    extern __shared__ char smem_raw[];
    float*  cost     = (float*)smem_raw;                 // GG * CPAD floats
    double* shortest = (double*)(cost + GG * CPAD);      // QQ doubles
    double* u        = (double*)(shortest + QQ);         // GG doubles
    int*    path     = (int*)(u + GG);                   // QQ ints
    int*    row4col  = path + QQ;                        // QQ ints
    int*    col4row  = row4col + QQ;                     // GG ints
    int*    sr       = col4row + GG;                     // GG ints

    const int b    = blockIdx.x;
    const int lane = threadIdx.x;
    const double DINF = __longlong_as_double(0x7ff0000000000000LL);

    // ---- nactual_gt dtype detection: values are always >= 1, so if the
    // buffer is int64 (little-endian) every odd int32 word is 0.
    int n;
    {
        bool is64 = (nactRaw[1] == 0);
        n = is64 ? nactRaw[2 * b] : nactRaw[b];
        if (n > GG) n = GG;
        if (n < 0)  n = 0;
    }

    // ---- stage cost tile: cost[g][q] = -2 * gious[b, q, g]
    // coalesced global read (consecutive g), padded shared store (bank-free)
    const float* gb = gious + (size_t)b * QQ * GG;
    for (int idx = lane; idx < QQ * GG; idx += 32) {
        int q = idx >> 6;     // idx / GG
        int g = idx & 63;     // idx % GG
        cost[g * CPAD + q] = -2.0f * gb[idx];
    }

    // ---- init matching state
    double v[8];              // dual v for own columns q = lane + 32k
#pragma unroll
    for (int k = 0; k < 8; k++) v[k] = 0.0;
#pragma unroll
    for (int k = 0; k < 8; k++) row4col[lane + 32 * k] = -1;
    u[lane] = 0.0;  u[lane + 32] = 0.0;
    col4row[lane] = -1;  col4row[lane + 32] = -1;
    __syncwarp();

    for (int cur_row = 0; cur_row < n; cur_row++) {
        // per-row reset
        unsigned scanned = 0;   // bit k -> column lane + 32k is in SC
#pragma unroll
        for (int k = 0; k < 8; k++) shortest[lane + 32 * k] = DINF;
        sr[lane] = 0; sr[lane + 32] = 0;
        __syncwarp();

        int    i      = cur_row;
        double minval = 0.0;
        int    sink   = -1;

        for (int iter = 0; iter < QQ; iter++) {
            if (lane == 0) sr[i] = 1;
            const double ui = u[i];
            const float* crow = cost + i * CPAD;

            // relax all unscanned own columns:
            // r = ((min_val + cost) - u_i) - v_j   (same order as reference)
            double bestv = DINF;
            int    bestq = QQ;
#pragma unroll
            for (int k = 0; k < 8; k++) {
                const int q = lane + 32 * k;
                if (!((scanned >> k) & 1u)) {
                    double r = ((minval + (double)crow[q]) - ui) - v[k];
                    double s = shortest[q];
                    if (r < s) { s = r; shortest[q] = r; path[q] = i; }
                    if (s < bestv) { bestv = s; bestq = q; }
                    // note: k ascending => q ascending, so strict < keeps
                    // the lowest q on equality automatically
                }
            }

            // warp argmin (lexicographic: value, then lowest column index)
#pragma unroll
            for (int off = 16; off; off >>= 1) {
                double ov = __shfl_xor_sync(0xffffffffu, bestv, off);
                int    oq = __shfl_xor_sync(0xffffffffu, bestq, off);
                if (ov < bestv || (ov == bestv && oq < bestq)) { bestv = ov; bestq = oq; }
            }

            const int j = bestq;
            minval = bestv;
            if ((j & 31) == lane) scanned |= 1u << (j >> 5);   // SC[j] = true (owner lane)
            const int r4 = row4col[j];      // all lanes read same value
            if (r4 < 0) { sink = j; break; }
            i = r4;
        }

        __syncwarp();   // order shortest/path/sr writes before cross-lane reads

        // ---- dual updates
        // u[rows in SR, except cur_row] += minval - shortest[col4row[row]]
        for (int r = lane; r < n; r += 32) {
            if (sr[r] && r != cur_row) {
                u[r] += minval - shortest[col4row[r]];
            }
        }
        if (lane == 0) u[cur_row] += minval;
        // v[cols in SC] -= minval - shortest[col]   (register-local)
#pragma unroll
        for (int k = 0; k < 8; k++) {
            if ((scanned >> k) & 1u) {
                v[k] -= minval - shortest[lane + 32 * k];
            }
        }
        __syncwarp();

        // ---- augment along alternating path (serial, lane 0)
        if (lane == 0) {
            int j = sink;
            while (true) {
                int ii = path[j];
                row4col[j] = ii;
                int t = col4row[ii];
                col4row[ii] = j;
                j = t;
                if (ii == cur_row) break;
            }
        }
        __syncwarp();
    }

    // ---- outputs
    float* out_ind  = out + (size_t)b * QQ;
    float* out_mask = out + (size_t)BB * QQ + (size_t)b * QQ;
#pragma unroll
    for (int k = 0; k < 8; k++) {
        const int q = lane + 32 * k;
        const int r = row4col[q];
        out_ind[q]  = (r >= 0) ? (float)r : 0.0f;
        out_mask[q] = (r >= 0) ? 1.0f : 0.0f;
    }
}

extern "C" void kernel_launch(void* const* d_in, const int* in_sizes, int n_in,
                              void* d_out, int out_size) {
    // Locate the two inputs that actually matter by element count:
    //   gious:      B*Q*G = 1,048,576
    //   nactual_gt: B     = 64
    const float* gious = nullptr;
    const int*   nact  = nullptr;
    for (int i = 0; i < n_in; i++) {
        if (in_sizes[i] == BB * QQ * GG)      gious = (const float*)d_in[i];
        else if (in_sizes[i] == BB)           nact  = (const int*)d_in[i];
    }

    const size_t smem = (size_t)GG * CPAD * sizeof(float)   // cost
                      + (size_t)QQ * sizeof(double)         // shortest
                      + (size_t)GG * sizeof(double)         // u
                      + (size_t)QQ * sizeof(int)            // path
                      + (size_t)QQ * sizeof(int)            // row4col
                      + (size_t)GG * sizeof(int)            // col4row
                      + (size_t)GG * sizeof(int);           // sr

    cudaFuncSetAttribute(matcher_lsa_kernel,
                         cudaFuncAttributeMaxDynamicSharedMemorySize, (int)smem);

    matcher_lsa_kernel<<<BB, 32, smem>>>(gious, nact, (float*)d_out);
}

// round 2
// speedup vs baseline: 4.3866x; 4.3866x over previous
#include <cuda_runtime.h>
#include <cuda_bf16.h>

// Matcher: final_cost = -2 * gious  (class_mat in reference is dead code).
// Per batch b: Hungarian (Jonker-Volgenant) on cost[g][q] = -2*gious[b,q,g],
// rows g in [0, nactual_gt[b]), cols q in [0, 256).
// All arithmetic in float32: the optimal assignment is unique w.p. 1 for
// continuous random costs, so f32 rounding does not change the output.
// Outputs (concatenated float32):
//   out[0     .. B*Q)  = per_prop_gt_inds
//   out[B*Q .. 2*B*Q)  = proposal_matched_mask

#define BB 64
#define QQ 256
#define GG 64
#define CPAD 257   // padded cost row stride (floats)

__device__ __forceinline__ unsigned redux_min_u32(unsigned x) {
    unsigned r;
    asm volatile("redux.sync.min.u32 %0, %1, 0xffffffff;" : "=r"(r) : "r"(x));
    return r;
}

// monotonic float -> u32 key (total order, -inf..+inf ascending)
__device__ __forceinline__ unsigned f2k(float f) {
    unsigned x = __float_as_uint(f);
    return (x & 0x80000000u) ? ~x : (x | 0x80000000u);
}
__device__ __forceinline__ float k2f(unsigned k) {
    unsigned x = (k & 0x80000000u) ? (k ^ 0x80000000u) : ~k;
    return __uint_as_float(x);
}

__global__ void __launch_bounds__(32, 1) matcher_lsa_kernel(
    const float* __restrict__ gious,   // [B, Q, G] float32
    const int*   __restrict__ nactRaw, // int32 view of nactual_gt (int32 or int64)
    float*       __restrict__ out)     // [2*B*Q] float32
{
    extern __shared__ char smem_raw[];
    float* cost    = (float*)smem_raw;            // GG * CPAD
    float* shsh    = cost + GG * CPAD;            // QQ  shortest (mirror of regs)
    float* u       = shsh + QQ;                   // GG
    int*   path    = (int*)(u + GG);              // QQ
    int*   row4col = path + QQ;                   // QQ
    int*   col4row = row4col + QQ;                // GG
    int*   srsh    = col4row + GG;                // GG

    const int b    = blockIdx.x;
    const int lane = threadIdx.x;
    const float FINF = __uint_as_float(0x7f800000u);

    // nactual_gt dtype detection (values >= 1 always, so int64 -> odd words are 0)
    int n;
    {
        bool is64 = (nactRaw[1] == 0);
        n = is64 ? nactRaw[2 * b] : nactRaw[b];
        if (n > GG) n = GG;
        if (n < 0)  n = 0;
    }

    // stage cost tile: cost[g][q] = -2 * gious[b, q, g]  (vectorized global read)
    {
        const float4* gb4 = (const float4*)(gious + (size_t)b * QQ * GG);
        for (int t = lane; t < (QQ * GG) / 4; t += 32) {
            float4 val = gb4[t];
            int q = t >> 4;            // t*4 / 64
            int g = (t & 15) << 2;     // (t*4) % 64
            cost[(g + 0) * CPAD + q] = -2.0f * val.x;
            cost[(g + 1) * CPAD + q] = -2.0f * val.y;
            cost[(g + 2) * CPAD + q] = -2.0f * val.z;
            cost[(g + 3) * CPAD + q] = -2.0f * val.w;
        }
    }

    // init state
    float vv[8];   // dual v for own columns q = lane + 32k
    float sh[8];   // shortest for own columns
#pragma unroll
    for (int k = 0; k < 8; k++) vv[k] = 0.0f;
#pragma unroll
    for (int k = 0; k < 8; k++) row4col[lane + 32 * k] = -1;
    u[lane] = 0.0f;  u[lane + 32] = 0.0f;
    col4row[lane] = -1;  col4row[lane + 32] = -1;
    __syncwarp();

    for (int cur_row = 0; cur_row < n; cur_row++) {
        unsigned scanned = 0;   // bit k -> own column lane+32k is in SC
#pragma unroll
        for (int k = 0; k < 8; k++) sh[k] = FINF;
        srsh[lane] = 0; srsh[lane + 32] = 0;
        __syncwarp();

        int   i      = cur_row;
        float minval = 0.0f;
        int   sink;

        while (true) {
            if (lane == 0) srsh[i] = 1;
            const float ui = u[i];
            const float* crow = cost + i * CPAD;

            // relax unscanned own columns; track lane-local min value
            float bestv = FINF;
#pragma unroll
            for (int k = 0; k < 8; k++) {
                const bool un = !((scanned >> k) & 1u);
                const float c = crow[lane + 32 * k];
                const float r = ((minval + c) - ui) - vv[k];
                if (un && r < sh[k]) { sh[k] = r; path[lane + 32 * k] = i; }
                const float cd = un ? sh[k] : FINF;
                bestv = fminf(bestv, cd);
            }

            // global min value via redux on ordered key
            const unsigned gkey  = redux_min_u32(f2k(bestv));
            const float    gminf = k2f(gkey);

            // lowest column index achieving the min (tie -> lowest q, as reference)
            unsigned cq = 0xFFFFFFFFu;
#pragma unroll
            for (int k = 0; k < 8; k++) {
                const bool m = (!((scanned >> k) & 1u)) && (sh[k] == gminf);
                cq = min(cq, m ? (unsigned)(lane + 32 * k) : 0xFFFFFFFFu);
            }
            const int j = (int)redux_min_u32(cq);

            minval = gminf;
            if ((j & 31) == lane) scanned |= 1u << (j >> 5);   // SC[j] = true
            const int r4 = row4col[j];
            if (r4 < 0) { sink = j; break; }
            i = r4;
        }

        // write back shortest for scanned columns (only ones dual update reads)
#pragma unroll
        for (int k = 0; k < 8; k++)
            if ((scanned >> k) & 1u) shsh[lane + 32 * k] = sh[k];
        __syncwarp();

        // dual updates
        for (int r = lane; r < n; r += 32) {
            if (srsh[r] && r != cur_row) {
                u[r] += minval - shsh[col4row[r]];
            }
        }
        if (lane == 0) u[cur_row] += minval;
#pragma unroll
        for (int k = 0; k < 8; k++) {
            if ((scanned >> k) & 1u) vv[k] -= minval - sh[k];
        }
        __syncwarp();

        // augment along alternating path (serial, lane 0)
        if (lane == 0) {
            int j = sink;
            while (true) {
                int ii = path[j];
                row4col[j] = ii;
                int t = col4row[ii];
                col4row[ii] = j;
                j = t;
                if (ii == cur_row) break;
            }
        }
        __syncwarp();
    }

    // outputs
    float* out_ind  = out + (size_t)b * QQ;
    float* out_mask = out + (size_t)BB * QQ + (size_t)b * QQ;
#pragma unroll
    for (int k = 0; k < 8; k++) {
        const int q = lane + 32 * k;
        const int r = row4col[q];
        out_ind[q]  = (r >= 0) ? (float)r : 0.0f;
        out_mask[q] = (r >= 0) ? 1.0f : 0.0f;
    }
}

extern "C" void kernel_launch(void* const* d_in, const int* in_sizes, int n_in,
                              void* d_out, int out_size) {
    const float* gious = nullptr;
    const int*   nact  = nullptr;
    for (int i = 0; i < n_in; i++) {
        if (in_sizes[i] == BB * QQ * GG)      gious = (const float*)d_in[i];
        else if (in_sizes[i] == BB)           nact  = (const int*)d_in[i];
    }

    const size_t smem = (size_t)GG * CPAD * sizeof(float)   // cost
                      + (size_t)QQ * sizeof(float)          // shortest mirror
                      + (size_t)GG * sizeof(float)          // u
                      + (size_t)QQ * sizeof(int)            // path
                      + (size_t)QQ * sizeof(int)            // row4col
                      + (size_t)GG * sizeof(int)            // col4row
                      + (size_t)GG * sizeof(int);           // sr

    cudaFuncSetAttribute(matcher_lsa_kernel,
                         cudaFuncAttributeMaxDynamicSharedMemorySize, (int)smem);

    matcher_lsa_kernel<<<BB, 32, smem>>>(gious, nact, (float*)d_out);
}

// round 3
// speedup vs baseline: 8.2587x; 1.8827x over previous
#include <cuda_runtime.h>
#include <cuda_bf16.h>

// Matcher: final_cost = -2 * gious (class_mat in reference is dead code).
// Per batch b: exact rectangular LSA (Jonker-Volgenant with greedy row-min
// initialization) on cost[g][q] = -2*gious[b,q,g], g < nactual_gt[b], q < 256.
// The optimal assignment is unique w.p. 1 for continuous random costs, so any
// exact algorithm (and f32 arithmetic) reproduces the reference output.
// Outputs (concatenated float32):
//   out[0     .. B*Q)  = per_prop_gt_inds
//   out[B*Q .. 2*B*Q)  = proposal_matched_mask

#define BB 64
#define QQ 256
#define GG 64
#define CPAD 257   // padded cost row stride (floats)

__device__ __forceinline__ unsigned redux_min_u32(unsigned x) {
    unsigned r;
    asm volatile("redux.sync.min.u32 %0, %1, 0xffffffff;" : "=r"(r) : "r"(x));
    return r;
}

// monotonic float -> u32 key (total order ascending)
__device__ __forceinline__ unsigned f2k(float f) {
    unsigned x = __float_as_uint(f);
    return (x & 0x80000000u) ? ~x : (x | 0x80000000u);
}
__device__ __forceinline__ float k2f(unsigned k) {
    unsigned x = (k & 0x80000000u) ? (k ^ 0x80000000u) : ~k;
    return __uint_as_float(x);
}

__global__ void __launch_bounds__(32, 1) matcher_lsa_kernel(
    const float* __restrict__ gious,   // [B, Q, G] float32
    const int*   __restrict__ nactRaw, // int32 view of nactual_gt (int32 or int64)
    float*       __restrict__ out)     // [2*B*Q] float32
{
    extern __shared__ char smem_raw[];
    float* cost    = (float*)smem_raw;            // GG * CPAD
    float* shsh    = cost + GG * CPAD;            // QQ shortest mirror
    float* u       = shsh + QQ;                   // GG
    int*   path    = (int*)(u + GG);              // QQ
    int*   row4col = path + QQ;                   // QQ
    int*   col4row = row4col + QQ;                // GG
    int*   srsh    = col4row + GG;                // GG
    int*   rmArg   = srsh + GG;                   // GG row argmin

    const int b    = blockIdx.x;
    const int lane = threadIdx.x;
    const float FINF = __uint_as_float(0x7f800000u);

    // nactual_gt dtype detection (values >= 1, so int64 -> odd words 0)
    int n;
    {
        bool is64 = (nactRaw[1] == 0);
        n = is64 ? nactRaw[2 * b] : nactRaw[b];
        if (n > GG) n = GG;
        if (n < 0)  n = 0;
    }

    // ---- stage cost tile: cost[g][q] = -2 * gious[b, q, g]
    {
        const float4* gb4 = (const float4*)(gious + (size_t)b * QQ * GG);
        for (int t = lane; t < (QQ * GG) / 4; t += 32) {
            float4 val = gb4[t];
            int q = t >> 4;
            int g = (t & 15) << 2;
            cost[(g + 0) * CPAD + q] = -2.0f * val.x;
            cost[(g + 1) * CPAD + q] = -2.0f * val.y;
            cost[(g + 2) * CPAD + q] = -2.0f * val.z;
            cost[(g + 3) * CPAD + q] = -2.0f * val.w;
        }
    }

    // ---- init matching state
    float vv[8];   // dual v for own columns q = lane + 32k (stays 0 after init)
    float sh[8];   // shortest for own columns
    int   r4c[8];  // register copy of row4col for own columns
#pragma unroll
    for (int k = 0; k < 8; k++) vv[k] = 0.0f;
#pragma unroll
    for (int k = 0; k < 8; k++) row4col[lane + 32 * k] = -1;
    col4row[lane] = -1;  col4row[lane + 32] = -1;
    __syncwarp();

    // ---- JV init: u[r] = row min; greedy assign argmin column if free.
    // Lane handles rows lane and lane+32 (CPAD stride -> conflict-free).
#pragma unroll
    for (int h = 0; h < 2; h++) {
        const int r = lane + 32 * h;
        const float* crow = cost + r * CPAD;
        float mv = FINF; int mq = 0;
        for (int q = 0; q < QQ; q++) {
            float c = crow[q];
            if (c < mv) { mv = c; mq = q; }   // strict < keeps lowest q
        }
        u[r] = mv;
        rmArg[r] = mq;
    }
    __syncwarp();
    if (lane == 0) {
        for (int i = 0; i < n; i++) {
            int j = rmArg[i];
            if (row4col[j] < 0) { row4col[j] = i; col4row[i] = j; }
        }
    }
    __syncwarp();
#pragma unroll
    for (int k = 0; k < 8; k++) r4c[k] = row4col[lane + 32 * k];

    // ---- augmentation loop for remaining unassigned rows
    for (int cur_row = 0; cur_row < n; cur_row++) {
        if (col4row[cur_row] >= 0) continue;

        unsigned scanned = 0;
#pragma unroll
        for (int k = 0; k < 8; k++) sh[k] = FINF;
        srsh[lane] = 0; srsh[lane + 32] = 0;
        __syncwarp();

        int   i      = cur_row;
        float minval = 0.0f;
        int   sink;

        while (true) {
            if (lane == 0) srsh[i] = 1;
            const float ui = u[i];
            const float* crow = cost + i * CPAD;

            float bestv = FINF;
#pragma unroll
            for (int k = 0; k < 8; k++) {
                const bool un = !((scanned >> k) & 1u);
                const float c = crow[lane + 32 * k];
                const float r = ((minval + c) - ui) - vv[k];
                if (un && r < sh[k]) { sh[k] = r; path[lane + 32 * k] = i; }
                bestv = fminf(bestv, un ? sh[k] : FINF);
            }

            // global min value
            const unsigned gkey  = redux_min_u32(f2k(bestv));
            const float    gminf = k2f(gkey);

            // argmin column packed with its row4col (from registers):
            // key = (q << 7) | (row4col[q] + 1); min -> lowest q, plus next i
            unsigned key2 = 0xFFFFFFFFu;
#pragma unroll
            for (int k = 0; k < 8; k++) {
                const bool m = (!((scanned >> k) & 1u)) && (sh[k] == gminf);
                const unsigned cand = ((unsigned)(lane + 32 * k) << 7)
                                    | (unsigned)(r4c[k] + 1);
                key2 = min(key2, m ? cand : 0xFFFFFFFFu);
            }
            const unsigned packed = redux_min_u32(key2);
            const int j  = (int)(packed >> 7);
            const int r4 = (int)(packed & 127u) - 1;

            minval = gminf;
            if ((j & 31) == lane) scanned |= 1u << (j >> 5);
            if (r4 < 0) { sink = j; break; }
            i = r4;
        }

        // write back shortest for scanned columns (dual update reads them)
#pragma unroll
        for (int k = 0; k < 8; k++)
            if ((scanned >> k) & 1u) shsh[lane + 32 * k] = sh[k];
        __syncwarp();

        // dual updates
        for (int r = lane; r < n; r += 32) {
            if (srsh[r] && r != cur_row) {
                u[r] += minval - shsh[col4row[r]];
            }
        }
        if (lane == 0) u[cur_row] += minval;
#pragma unroll
        for (int k = 0; k < 8; k++) {
            if ((scanned >> k) & 1u) vv[k] -= minval - sh[k];
        }
        __syncwarp();

        // augment along alternating path (serial, lane 0)
        if (lane == 0) {
            int j = sink;
            while (true) {
                int ii = path[j];
                row4col[j] = ii;
                int t = col4row[ii];
                col4row[ii] = j;
                j = t;
                if (ii == cur_row) break;
            }
        }
        __syncwarp();
        // refresh register row4col copies
#pragma unroll
        for (int k = 0; k < 8; k++) r4c[k] = row4col[lane + 32 * k];
    }

    // ---- outputs
    float* out_ind  = out + (size_t)b * QQ;
    float* out_mask = out + (size_t)BB * QQ + (size_t)b * QQ;
#pragma unroll
    for (int k = 0; k < 8; k++) {
        const int q = lane + 32 * k;
        const int r = row4col[q];
        out_ind[q]  = (r >= 0) ? (float)r : 0.0f;
        out_mask[q] = (r >= 0) ? 1.0f : 0.0f;
    }
}

extern "C" void kernel_launch(void* const* d_in, const int* in_sizes, int n_in,
                              void* d_out, int out_size) {
    const float* gious = nullptr;
    const int*   nact  = nullptr;
    for (int i = 0; i < n_in; i++) {
        if (in_sizes[i] == BB * QQ * GG)      gious = (const float*)d_in[i];
        else if (in_sizes[i] == BB)           nact  = (const int*)d_in[i];
    }

    const size_t smem = (size_t)GG * CPAD * sizeof(float)   // cost
                      + (size_t)QQ * sizeof(float)          // shortest mirror
                      + (size_t)GG * sizeof(float)          // u
                      + (size_t)QQ * sizeof(int)            // path
                      + (size_t)QQ * sizeof(int)            // row4col
                      + (size_t)GG * sizeof(int)            // col4row
                      + (size_t)GG * sizeof(int)            // sr
                      + (size_t)GG * sizeof(int);           // row argmin

    cudaFuncSetAttribute(matcher_lsa_kernel,
                         cudaFuncAttributeMaxDynamicSharedMemorySize, (int)smem);

    matcher_lsa_kernel<<<BB, 32, smem>>>(gious, nact, (float*)d_out);
}

// round 4
// speedup vs baseline: 10.9554x; 1.3265x over previous
#include <cuda_runtime.h>
#include <cuda_bf16.h>

// Matcher: final_cost = -2 * gious (class_mat in reference is dead code).
// Per batch b: exact rectangular LSA (Jonker-Volgenant, greedy row-min init)
// on cost[g][q] = -2*gious[b,q,g], g < nactual_gt[b], q < 256.
// Optimal assignment is unique w.p. 1 for continuous random costs, so any
// exact algorithm / tie-break / f32 arithmetic reproduces the reference.
// Outputs (concatenated float32):
//   out[0     .. B*Q)  = per_prop_gt_inds
//   out[B*Q .. 2*B*Q)  = proposal_matched_mask

#define BB 64
#define QQ 256
#define GG 64
#define CPAD 257   // padded cost row stride (floats): lane-conflict-free both ways

__device__ __forceinline__ unsigned redux_min_u32(unsigned x) {
    unsigned r;
    asm volatile("redux.sync.min.u32 %0, %1, 0xffffffff;" : "=r"(r) : "r"(x));
    return r;
}
// monotonic float <-> u32 order-preserving key
__device__ __forceinline__ unsigned f2k(float f) {
    unsigned x = __float_as_uint(f);
    return (x & 0x80000000u) ? ~x : (x | 0x80000000u);
}
__device__ __forceinline__ float k2f(unsigned k) {
    unsigned x = (k & 0x80000000u) ? (k ^ 0x80000000u) : ~k;
    return __uint_as_float(x);
}

__global__ void __launch_bounds__(32, 1) matcher_lsa_kernel(
    const float* __restrict__ gious,   // [B, Q, G] float32
    const int*   __restrict__ nactRaw, // int32 view of nactual_gt
    float*       __restrict__ out)     // [2*B*Q] float32
{
    extern __shared__ char smem_raw[];
    float* cost    = (float*)smem_raw;            // GG * CPAD
    float* shsh    = cost + GG * CPAD;            // QQ shortest mirror (scanned only)
    float* u       = shsh + QQ;                   // GG
    int*   path    = (int*)(u + GG);              // QQ
    int*   row4col = path + QQ;                   // QQ
    int*   col4row = row4col + QQ;                // GG
    int*   claim   = col4row + GG;                // QQ greedy claims

    const int b    = blockIdx.x;
    const int lane = threadIdx.x;
    const float FINF = __uint_as_float(0x7f800000u);
    const unsigned FULL = 0xffffffffu;

    // nactual_gt dtype detection (values >= 1, int64 -> odd 32-bit words are 0)
    int n;
    {
        bool is64 = (nactRaw[1] == 0);
        n = is64 ? nactRaw[2 * b] : nactRaw[b];
        if (n > GG) n = GG;
        if (n < 0)  n = 0;
    }

    // ---- stage cost tile: cost[g][q] = -2 * gious[b, q, g]
    {
        const float4* gb4 = (const float4*)(gious + (size_t)b * QQ * GG);
        for (int t = lane; t < (QQ * GG) / 4; t += 32) {
            float4 val = gb4[t];
            int q = t >> 4;
            int g = (t & 15) << 2;
            cost[(g + 0) * CPAD + q] = -2.0f * val.x;
            cost[(g + 1) * CPAD + q] = -2.0f * val.y;
            cost[(g + 2) * CPAD + q] = -2.0f * val.z;
            cost[(g + 3) * CPAD + q] = -2.0f * val.w;
        }
    }

    // ---- base init
    float vv[8];   // dual v for own columns q = lane + 32k
    float sh[8];   // shortest for own columns
    int   r4c[8];  // register mirror of row4col for own columns
#pragma unroll
    for (int k = 0; k < 8; k++) vv[k] = 0.0f;
#pragma unroll
    for (int k = 0; k < 8; k++) {
        row4col[lane + 32 * k] = -1;
        claim[lane + 32 * k]   = 0x7fffffff;
    }
    col4row[lane] = -1;  col4row[lane + 32] = -1;
    __syncwarp();

    // ---- row mins (u init) + per-row argmin, 4 independent compare chains
    int rm[2];
#pragma unroll
    for (int h = 0; h < 2; h++) {
        const int r = lane + 32 * h;
        const float* crow = cost + r * CPAD;
        float m0 = FINF, m1 = FINF, m2 = FINF, m3 = FINF;
        int   q0 = 0,    q1 = 1,    q2 = 2,    q3 = 3;
        for (int q = 0; q < QQ; q += 4) {
            float c0 = crow[q], c1 = crow[q + 1], c2 = crow[q + 2], c3 = crow[q + 3];
            if (c0 < m0) { m0 = c0; q0 = q; }
            if (c1 < m1) { m1 = c1; q1 = q + 1; }
            if (c2 < m2) { m2 = c2; q2 = q + 2; }
            if (c3 < m3) { m3 = c3; q3 = q + 3; }
        }
        float mv = m0; int mq = q0;
        if (m1 < mv) { mv = m1; mq = q1; }
        if (m2 < mv) { mv = m2; mq = q2; }
        if (m3 < mv) { mv = m3; mq = q3; }
        u[r]  = mv;
        rm[h] = mq;
    }
    __syncwarp();

    // ---- parallel greedy assignment: lowest row wins each claimed column
    if (lane < n)      atomicMin(&claim[rm[0]], lane);
    if (lane + 32 < n) atomicMin(&claim[rm[1]], lane + 32);
    __syncwarp();
    bool a0 = (lane < n)      && (claim[rm[0]] == lane);
    bool a1 = (lane + 32 < n) && (claim[rm[1]] == lane + 32);
    if (a0) { col4row[lane]      = rm[0]; row4col[rm[0]] = lane; }
    if (a1) { col4row[lane + 32] = rm[1]; row4col[rm[1]] = lane + 32; }
    unsigned bal0 = __ballot_sync(FULL, a0);
    unsigned bal1 = __ballot_sync(FULL, a1);
    unsigned long long nmask =
        (n >= 64) ? ~0ull : ((1ull << n) - 1ull);
    unsigned long long free_rows =
        ~(((unsigned long long)bal1 << 32) | (unsigned long long)bal0) & nmask;
    __syncwarp();
#pragma unroll
    for (int k = 0; k < 8; k++) r4c[k] = row4col[lane + 32 * k];

    // ---- augmentation for each remaining free row
    while (free_rows) {
        const int cur_row = __ffsll((long long)free_rows) - 1;
        free_rows &= free_rows - 1;

        unsigned scanned = 0;   // bit k -> own column lane+32k is in SC
        unsigned long long sr = 0;  // scanned-row set (uniform across lanes)
#pragma unroll
        for (int k = 0; k < 8; k++) sh[k] = FINF;

        int   i      = cur_row;
        float minval = 0.0f;
        int   sink;

        while (true) {
            sr |= 1ull << i;
            const float base = minval - u[i];          // LDS + FADD (scalar)
            const float* crow = cost + i * CPAD;

            float cand[8];
#pragma unroll
            for (int k = 0; k < 8; k++) {
                const int q = lane + 32 * k;
                const bool un = !((scanned >> k) & 1u);
                const float r = (base + crow[q]) - vv[k];
                if (un && r < sh[k]) { sh[k] = r; path[q] = i; }
                cand[k] = un ? sh[k] : FINF;
            }
            // lane-local min value (tree)
            float m01 = fminf(cand[0], cand[1]), m23 = fminf(cand[2], cand[3]);
            float m45 = fminf(cand[4], cand[5]), m67 = fminf(cand[6], cand[7]);
            float bv  = fminf(fminf(m01, m23), fminf(m45, m67));
            const unsigned key = f2k(bv);

            // lane-local argmin pack (parallel with redux): (q<<9)|(row4col[q]+1)
            unsigned pk = 0xFFFFFFFFu;
#pragma unroll
            for (int k = 0; k < 8; k++) {
                const unsigned c = ((unsigned)(lane + 32 * k) << 9)
                                 | (unsigned)(r4c[k] + 1);
                pk = min(pk, (cand[k] == bv) ? c : 0xFFFFFFFFu);
            }

            const unsigned gkey   = redux_min_u32(key);
            const unsigned pk2    = (key == gkey) ? pk : 0xFFFFFFFFu;
            const unsigned packed = redux_min_u32(pk2);
            minval = k2f(gkey);

            const int j  = (int)(packed >> 9);
            const int r4 = (int)(packed & 511u) - 1;
            if ((j & 31) == lane) scanned |= 1u << (j >> 5);   // SC[j]
            if (r4 < 0) { sink = j; break; }
            i = r4;
        }

        // write back shortest for scanned columns (dual u update reads them)
#pragma unroll
        for (int k = 0; k < 8; k++)
            if ((scanned >> k) & 1u) shsh[lane + 32 * k] = sh[k];
        __syncwarp();

        // dual updates
#pragma unroll
        for (int h = 0; h < 2; h++) {
            const int r = lane + 32 * h;
            if (((sr >> r) & 1ull) && r != cur_row) {
                u[r] += minval - shsh[col4row[r]];
            }
        }
        if (lane == 0) u[cur_row] += minval;
#pragma unroll
        for (int k = 0; k < 8; k++) {
            if ((scanned >> k) & 1u) vv[k] -= minval - sh[k];
        }
        __syncwarp();

        // augment along alternating path (serial, lane 0)
        if (lane == 0) {
            int j = sink;
            while (true) {
                int ii = path[j];
                row4col[j] = ii;
                int t = col4row[ii];
                col4row[ii] = j;
                j = t;
                if (ii == cur_row) break;
            }
        }
        __syncwarp();
#pragma unroll
        for (int k = 0; k < 8; k++) r4c[k] = row4col[lane + 32 * k];
    }

    // ---- outputs
    float* out_ind  = out + (size_t)b * QQ;
    float* out_mask = out + (size_t)BB * QQ + (size_t)b * QQ;
#pragma unroll
    for (int k = 0; k < 8; k++) {
        const int q = lane + 32 * k;
        const int r = row4col[q];
        out_ind[q]  = (r >= 0) ? (float)r : 0.0f;
        out_mask[q] = (r >= 0) ? 1.0f : 0.0f;
    }
}

extern "C" void kernel_launch(void* const* d_in, const int* in_sizes, int n_in,
                              void* d_out, int out_size) {
    const float* gious = nullptr;
    const int*   nact  = nullptr;
    for (int i = 0; i < n_in; i++) {
        if (in_sizes[i] == BB * QQ * GG)      gious = (const float*)d_in[i];
        else if (in_sizes[i] == BB)           nact  = (const int*)d_in[i];
    }

    const size_t smem = (size_t)GG * CPAD * sizeof(float)   // cost
                      + (size_t)QQ * sizeof(float)          // shortest mirror
                      + (size_t)GG * sizeof(float)          // u
                      + (size_t)QQ * sizeof(int)            // path
                      + (size_t)QQ * sizeof(int)            // row4col
                      + (size_t)GG * sizeof(int)            // col4row
                      + (size_t)QQ * sizeof(int);           // claim

    cudaFuncSetAttribute(matcher_lsa_kernel,
                         cudaFuncAttributeMaxDynamicSharedMemorySize, (int)smem);

    matcher_lsa_kernel<<<BB, 32, smem>>>(gious, nact, (float*)d_out);
}

// round 5
// speedup vs baseline: 12.9352x; 1.1807x over previous
#include <cuda_runtime.h>
#include <cuda_bf16.h>

// Matcher: final_cost = -2 * gious (class_mat in reference is dead code).
// Per batch b: exact rectangular LSA, full Jonker-Volgenant:
//   row-min greedy init -> augmenting row reduction (ARR) -> Dijkstra augment.
// Duals stay feasible with slack-0 assignments in every phase, so the result
// is the exact optimum; optimum is unique w.p. 1 for continuous random costs,
// hence identical to the scipy-style reference.
// Outputs (concatenated float32):
//   out[0     .. B*Q)  = per_prop_gt_inds
//   out[B*Q .. 2*B*Q)  = proposal_matched_mask

#define BB 64
#define QQ 256
#define GG 64
#define CPAD 257   // padded cost row stride (floats)

__device__ __forceinline__ unsigned redux_min_u32(unsigned x) {
    unsigned r;
    asm volatile("redux.sync.min.u32 %0, %1, 0xffffffff;" : "=r"(r) : "r"(x));
    return r;
}
// monotonic float <-> u32 order-preserving key
__device__ __forceinline__ unsigned f2k(float f) {
    unsigned x = __float_as_uint(f);
    return (x & 0x80000000u) ? ~x : (x | 0x80000000u);
}
__device__ __forceinline__ float k2f(unsigned k) {
    unsigned x = (k & 0x80000000u) ? (k ^ 0x80000000u) : ~k;
    return __uint_as_float(x);
}

__global__ void __launch_bounds__(32, 1) matcher_lsa_kernel(
    const float* __restrict__ gious,   // [B, Q, G] float32
    const int*   __restrict__ nactRaw, // int32 view of nactual_gt
    float*       __restrict__ out)     // [2*B*Q] float32
{
    extern __shared__ char smem_raw[];
    float* cost    = (float*)smem_raw;            // GG * CPAD
    float* shsh    = cost + GG * CPAD;            // QQ shortest mirror
    float* u       = shsh + QQ;                   // GG
    int*   path    = (int*)(u + GG);              // QQ
    int*   row4col = path + QQ;                   // QQ
    int*   col4row = row4col + QQ;                // GG
    int*   claim   = col4row + GG;                // QQ greedy claims
    int*   rmArg   = claim + QQ;                  // GG row argmins

    const int b    = blockIdx.x;
    const int lane = threadIdx.x;
    const float FINF = __uint_as_float(0x7f800000u);
    const unsigned FULL = 0xffffffffu;

    // nactual_gt dtype detection (values >= 1, int64 -> odd 32-bit words are 0)
    int n;
    {
        bool is64 = (nactRaw[1] == 0);
        n = is64 ? nactRaw[2 * b] : nactRaw[b];
        if (n > GG) n = GG;
        if (n < 0)  n = 0;
    }

    // ---- init small state
    float vv[8];   // dual v for own columns q = lane + 32k
    float sh[8];   // shortest for own columns
    int   r4c[8];  // register mirror of row4col for own columns
#pragma unroll
    for (int k = 0; k < 8; k++) {
        vv[k] = 0.0f;
        row4col[lane + 32 * k] = -1;
        claim[lane + 32 * k]   = 0x7fffffff;
    }
    col4row[lane] = -1;  col4row[lane + 32] = -1;

    // ---- stage cost tile (cost[g][q] = -2*gious[b,q,g]) with fused row-min.
    // Lane covers rows g0..g0+3 (g0=(lane&15)*4) at columns q = 2*it + (lane>>4).
    {
        const float4* gb4 = (const float4*)(gious + (size_t)b * QQ * GG);
        const int g0 = (lane & 15) << 2;
        float m0 = FINF, m1 = FINF, m2 = FINF, m3 = FINF;
        int   a0 = 0,    a1 = 0,    a2 = 0,    a3 = 0;
        for (int t = lane; t < (QQ * GG) / 4; t += 32) {
            float4 val = gb4[t];
            const int q = t >> 4;
            const float c0 = -2.0f * val.x, c1 = -2.0f * val.y;
            const float c2 = -2.0f * val.z, c3 = -2.0f * val.w;
            cost[(g0 + 0) * CPAD + q] = c0;
            cost[(g0 + 1) * CPAD + q] = c1;
            cost[(g0 + 2) * CPAD + q] = c2;
            cost[(g0 + 3) * CPAD + q] = c3;
            if (c0 < m0) { m0 = c0; a0 = q; }
            if (c1 < m1) { m1 = c1; a1 = q; }
            if (c2 < m2) { m2 = c2; a2 = q; }
            if (c3 < m3) { m3 = c3; a3 = q; }
        }
        // merge with partner lane (same rows, other q parity); tie -> lowest q
#define MERGE16(m, a) { \
            float om = __shfl_xor_sync(FULL, m, 16); \
            int   oa = __shfl_xor_sync(FULL, a, 16); \
            if (om < m || (om == m && oa < a)) { m = om; a = oa; } }
        MERGE16(m0, a0) MERGE16(m1, a1) MERGE16(m2, a2) MERGE16(m3, a3)
#undef MERGE16
        if (lane < 16) {
            u[g0 + 0] = m0; rmArg[g0 + 0] = a0;
            u[g0 + 1] = m1; rmArg[g0 + 1] = a1;
            u[g0 + 2] = m2; rmArg[g0 + 2] = a2;
            u[g0 + 3] = m3; rmArg[g0 + 3] = a3;
        }
    }
    __syncwarp();

    // ---- parallel greedy assignment: lowest row wins each claimed column
    const int rm0 = rmArg[lane], rm1 = rmArg[lane + 32];
    if (lane < n)      atomicMin(&claim[rm0], lane);
    if (lane + 32 < n) atomicMin(&claim[rm1], lane + 32);
    __syncwarp();
    bool g_a0 = (lane < n)      && (claim[rm0] == lane);
    bool g_a1 = (lane + 32 < n) && (claim[rm1] == lane + 32);
    if (g_a0) { col4row[lane]      = rm0; row4col[rm0] = lane; }
    if (g_a1) { col4row[lane + 32] = rm1; row4col[rm1] = lane + 32; }
    unsigned bal0 = __ballot_sync(FULL, g_a0);
    unsigned bal1 = __ballot_sync(FULL, g_a1);
    const unsigned long long nmask = (n >= 64) ? ~0ull : ((1ull << n) - 1ull);
    unsigned long long free_rows =
        ~(((unsigned long long)bal1 << 32) | (unsigned long long)bal0) & nmask;
    __syncwarp();
#pragma unroll
    for (int k = 0; k < 8; k++) r4c[k] = row4col[lane + 32 * k];

    // ---- augmenting row reduction (JV): tighten duals, steal columns.
    // Any row it cannot settle goes to the exact Dijkstra phase below.
    unsigned long long dij = 0;
    {
        unsigned long long work = free_rows;
        int budget = 512;
        while (work) {
            int i = __ffsll((long long)work) - 1;
            work &= work - 1;
            bool active = true;
            while (active) {
                if (--budget < 0) { dij |= (1ull << i) | work; work = 0; break; }
                const float* crow = cost + i * CPAD;
                float rq[8];
#pragma unroll
                for (int k = 0; k < 8; k++) rq[k] = crow[lane + 32 * k] - vv[k];
                float p01 = fminf(rq[0], rq[1]), p23 = fminf(rq[2], rq[3]);
                float p45 = fminf(rq[4], rq[5]), p67 = fminf(rq[6], rq[7]);
                float bv  = fminf(fminf(p01, p23), fminf(p45, p67));
                const unsigned gkey = redux_min_u32(f2k(bv));
                const float u1 = k2f(gkey);
                unsigned pk = 0xFFFFFFFFu;
#pragma unroll
                for (int k = 0; k < 8; k++) {
                    const unsigned c = ((unsigned)(lane + 32 * k) << 9)
                                     | (unsigned)(r4c[k] + 1);
                    pk = min(pk, (rq[k] == u1) ? c : 0xFFFFFFFFu);
                }
                const unsigned packed = redux_min_u32(pk);
                const int j1 = (int)(packed >> 9);
                const int k1 = (int)(packed & 511u) - 1;

                // second min with j1 masked out
                if ((j1 & 31) == lane) rq[j1 >> 5] = FINF;
                float s01 = fminf(rq[0], rq[1]), s23 = fminf(rq[2], rq[3]);
                float s45 = fminf(rq[4], rq[5]), s67 = fminf(rq[6], rq[7]);
                float bv2 = fminf(fminf(s01, s23), fminf(s45, s67));
                const unsigned gkey2 = redux_min_u32(f2k(bv2));
                const float u2 = k2f(gkey2);

                if (lane == 0) u[i] = u2;

                if (gkey < gkey2) {           // u1 < u2: take j1 (steal if held)
                    if ((j1 & 31) == lane) { vv[j1 >> 5] -= (u2 - u1); r4c[j1 >> 5] = i; }
                    if (lane == 0) {
                        row4col[j1] = i; col4row[i] = j1;
                        if (k1 >= 0) col4row[k1] = -1;
                    }
                    if (k1 >= 0) i = k1;       // continue with displaced row
                    else         active = false;
                } else {                       // u1 == u2
                    if (k1 < 0) {              // j1 free: take it (slack 0)
                        if ((j1 & 31) == lane) r4c[j1 >> 5] = i;
                        if (lane == 0) { row4col[j1] = i; col4row[i] = j1; }
                        active = false;
                    } else {
                        // j2 = next col with value u2 (j1 already masked)
                        unsigned pk2 = 0xFFFFFFFFu;
#pragma unroll
                        for (int k = 0; k < 8; k++) {
                            const unsigned c = ((unsigned)(lane + 32 * k) << 9)
                                             | (unsigned)(r4c[k] + 1);
                            pk2 = min(pk2, (rq[k] == u2) ? c : 0xFFFFFFFFu);
                        }
                        const unsigned packed2 = redux_min_u32(pk2);
                        const int j2  = (int)(packed2 >> 9);
                        const int k2r = (int)(packed2 & 511u) - 1;
                        if (k2r < 0) {         // j2 free: take it (slack 0)
                            if ((j2 & 31) == lane) r4c[j2 >> 5] = i;
                            if (lane == 0) { row4col[j2] = i; col4row[i] = j2; }
                        } else {
                            dij |= 1ull << i;  // defer to Dijkstra
                        }
                        active = false;
                    }
                }
            }
        }
    }
    __syncwarp();

    // ---- exact Dijkstra augmentation for remaining rows
    while (dij) {
        const int cur_row = __ffsll((long long)dij) - 1;
        dij &= dij - 1;

        unsigned scanned = 0;          // bit k -> own column lane+32k in SC
        unsigned long long sr = 0;     // scanned-row set (uniform)
#pragma unroll
        for (int k = 0; k < 8; k++) sh[k] = FINF;

        int   i      = cur_row;
        float minval = 0.0f;
        int   sink;

        while (true) {
            sr |= 1ull << i;
            const float base = minval - u[i];
            const float* crow = cost + i * CPAD;

            float cand[8];
#pragma unroll
            for (int k = 0; k < 8; k++) {
                const int q = lane + 32 * k;
                const bool un = !((scanned >> k) & 1u);
                const float r = (base + crow[q]) - vv[k];
                if (un && r < sh[k]) { sh[k] = r; path[q] = i; }
                cand[k] = un ? sh[k] : FINF;
            }
            float m01 = fminf(cand[0], cand[1]), m23 = fminf(cand[2], cand[3]);
            float m45 = fminf(cand[4], cand[5]), m67 = fminf(cand[6], cand[7]);
            float bv  = fminf(fminf(m01, m23), fminf(m45, m67));
            const unsigned key = f2k(bv);

            unsigned pk = 0xFFFFFFFFu;
#pragma unroll
            for (int k = 0; k < 8; k++) {
                const unsigned c = ((unsigned)(lane + 32 * k) << 9)
                                 | (unsigned)(r4c[k] + 1);
                pk = min(pk, (cand[k] == bv) ? c : 0xFFFFFFFFu);
            }

            const unsigned gkey   = redux_min_u32(key);
            const unsigned pk2    = (key == gkey) ? pk : 0xFFFFFFFFu;
            const unsigned packed = redux_min_u32(pk2);
            minval = k2f(gkey);

            const int j  = (int)(packed >> 9);
            const int r4 = (int)(packed & 511u) - 1;
            if ((j & 31) == lane) scanned |= 1u << (j >> 5);
            if (r4 < 0) { sink = j; break; }
            i = r4;
        }

        // write back shortest for scanned columns (dual u update reads them)
#pragma unroll
        for (int k = 0; k < 8; k++)
            if ((scanned >> k) & 1u) shsh[lane + 32 * k] = sh[k];
        __syncwarp();

        // dual updates
#pragma unroll
        for (int h = 0; h < 2; h++) {
            const int r = lane + 32 * h;
            if (((sr >> r) & 1ull) && r != cur_row) {
                u[r] += minval - shsh[col4row[r]];
            }
        }
        if (lane == 0) u[cur_row] += minval;
#pragma unroll
        for (int k = 0; k < 8; k++) {
            if ((scanned >> k) & 1u) vv[k] -= minval - sh[k];
        }
        __syncwarp();

        // augment along alternating path (serial, lane 0)
        if (lane == 0) {
            int j = sink;
            while (true) {
                int ii = path[j];
                row4col[j] = ii;
                int t = col4row[ii];
                col4row[ii] = j;
                j = t;
                if (ii == cur_row) break;
            }
        }
        __syncwarp();
#pragma unroll
        for (int k = 0; k < 8; k++) r4c[k] = row4col[lane + 32 * k];
    }

    // ---- outputs
    float* out_ind  = out + (size_t)b * QQ;
    float* out_mask = out + (size_t)BB * QQ + (size_t)b * QQ;
#pragma unroll
    for (int k = 0; k < 8; k++) {
        const int q = lane + 32 * k;
        const int r = row4col[q];
        out_ind[q]  = (r >= 0) ? (float)r : 0.0f;
        out_mask[q] = (r >= 0) ? 1.0f : 0.0f;
    }
}

extern "C" void kernel_launch(void* const* d_in, const int* in_sizes, int n_in,
                              void* d_out, int out_size) {
    const float* gious = nullptr;
    const int*   nact  = nullptr;
    for (int i = 0; i < n_in; i++) {
        if (in_sizes[i] == BB * QQ * GG)      gious = (const float*)d_in[i];
        else if (in_sizes[i] == BB)           nact  = (const int*)d_in[i];
    }

    const size_t smem = (size_t)GG * CPAD * sizeof(float)   // cost
                      + (size_t)QQ * sizeof(float)          // shortest mirror
                      + (size_t)GG * sizeof(float)          // u
                      + (size_t)QQ * sizeof(int)            // path
                      + (size_t)QQ * sizeof(int)            // row4col
                      + (size_t)GG * sizeof(int)            // col4row
                      + (size_t)QQ * sizeof(int)            // claim
                      + (size_t)GG * sizeof(int);           // row argmin

    cudaFuncSetAttribute(matcher_lsa_kernel,
                         cudaFuncAttributeMaxDynamicSharedMemorySize, (int)smem);

    matcher_lsa_kernel<<<BB, 32, smem>>>(gious, nact, (float*)d_out);
}

// round 6
// speedup vs baseline: 14.5330x; 1.1235x over previous
#include <cuda_runtime.h>
#include <cuda_bf16.h>

// Matcher: final_cost = -2 * gious (class_mat in reference is dead code).
// Per batch b: exact rectangular LSA, full Jonker-Volgenant:
//   row-min greedy init -> augmenting row reduction (ARR) -> Dijkstra augment.
// Duals stay feasible with slack-0 assignments in every phase, so the result
// is the exact optimum; optimum is unique w.p. 1 for continuous random costs,
// hence identical to the scipy-style reference.
// Outputs (concatenated float32):
//   out[0     .. B*Q)  = per_prop_gt_inds
//   out[B*Q .. 2*B*Q)  = proposal_matched_mask

#define BB 64
#define QQ 256
#define GG 64
#define CPAD 257   // padded cost row stride (floats)

__device__ __forceinline__ unsigned redux_min_u32(unsigned x) {
    unsigned r;
    asm volatile("redux.sync.min.u32 %0, %1, 0xffffffff;" : "=r"(r) : "r"(x));
    return r;
}
// monotonic float <-> u32 order-preserving key
__device__ __forceinline__ unsigned f2k(float f) {
    unsigned x = __float_as_uint(f);
    return (x & 0x80000000u) ? ~x : (x | 0x80000000u);
}
__device__ __forceinline__ float k2f(unsigned k) {
    unsigned x = (k & 0x80000000u) ? (k ^ 0x80000000u) : ~k;
    return __uint_as_float(x);
}

__global__ void __launch_bounds__(32, 1) matcher_lsa_kernel(
    const float* __restrict__ gious,   // [B, Q, G] float32
    const int*   __restrict__ nactRaw, // int32 view of nactual_gt
    float*       __restrict__ out)     // [2*B*Q] float32
{
    extern __shared__ char smem_raw[];
    float* cost    = (float*)smem_raw;            // GG * CPAD
    float* shsh    = cost + GG * CPAD;            // QQ shortest mirror
    float* u       = shsh + QQ;                   // GG
    int*   path    = (int*)(u + GG);              // QQ
    int*   row4col = path + QQ;                   // QQ
    int*   col4row = row4col + QQ;                // GG
    int*   claim   = col4row + GG;                // QQ greedy claims
    int*   rmArg   = claim + QQ;                  // GG row argmins

    const int b    = blockIdx.x;
    const int lane = threadIdx.x;
    const float FINF = __uint_as_float(0x7f800000u);
    const unsigned FULL = 0xffffffffu;

    // nactual_gt dtype detection (values >= 1, int64 -> odd 32-bit words are 0)
    int n;
    {
        bool is64 = (nactRaw[1] == 0);
        n = is64 ? nactRaw[2 * b] : nactRaw[b];
        if (n > GG) n = GG;
        if (n < 0)  n = 0;
    }

    // ---- init small state
    float vv[8];   // dual v for own columns q = lane + 32k
    float sh[8];   // shortest for own columns
    int   r4c[8];  // register mirror of row4col for own columns
#pragma unroll
    for (int k = 0; k < 8; k++) {
        vv[k] = 0.0f;
        row4col[lane + 32 * k] = -1;
        claim[lane + 32 * k]   = 0x7fffffff;
    }
    col4row[lane] = -1;  col4row[lane + 32] = -1;

    // ---- stage cost tile (cost[g][q] = -2*gious[b,q,g]) with fused row-min.
    {
        const float4* gb4 = (const float4*)(gious + (size_t)b * QQ * GG);
        const int g0 = (lane & 15) << 2;
        float m0 = FINF, m1 = FINF, m2 = FINF, m3 = FINF;
        int   a0 = 0,    a1 = 0,    a2 = 0,    a3 = 0;
        for (int t = lane; t < (QQ * GG) / 4; t += 32) {
            float4 val = gb4[t];
            const int q = t >> 4;
            const float c0 = -2.0f * val.x, c1 = -2.0f * val.y;
            const float c2 = -2.0f * val.z, c3 = -2.0f * val.w;
            cost[(g0 + 0) * CPAD + q] = c0;
            cost[(g0 + 1) * CPAD + q] = c1;
            cost[(g0 + 2) * CPAD + q] = c2;
            cost[(g0 + 3) * CPAD + q] = c3;
            if (c0 < m0) { m0 = c0; a0 = q; }
            if (c1 < m1) { m1 = c1; a1 = q; }
            if (c2 < m2) { m2 = c2; a2 = q; }
            if (c3 < m3) { m3 = c3; a3 = q; }
        }
#define MERGE16(m, a) { \
            float om = __shfl_xor_sync(FULL, m, 16); \
            int   oa = __shfl_xor_sync(FULL, a, 16); \
            if (om < m || (om == m && oa < a)) { m = om; a = oa; } }
        MERGE16(m0, a0) MERGE16(m1, a1) MERGE16(m2, a2) MERGE16(m3, a3)
#undef MERGE16
        if (lane < 16) {
            u[g0 + 0] = m0; rmArg[g0 + 0] = a0;
            u[g0 + 1] = m1; rmArg[g0 + 1] = a1;
            u[g0 + 2] = m2; rmArg[g0 + 2] = a2;
            u[g0 + 3] = m3; rmArg[g0 + 3] = a3;
        }
    }
    __syncwarp();

    // ---- parallel greedy assignment: lowest row wins each claimed column
    const int rm0 = rmArg[lane], rm1 = rmArg[lane + 32];
    if (lane < n)      atomicMin(&claim[rm0], lane);
    if (lane + 32 < n) atomicMin(&claim[rm1], lane + 32);
    __syncwarp();
    bool g_a0 = (lane < n)      && (claim[rm0] == lane);
    bool g_a1 = (lane + 32 < n) && (claim[rm1] == lane + 32);
    if (g_a0) { col4row[lane]      = rm0; row4col[rm0] = lane; }
    if (g_a1) { col4row[lane + 32] = rm1; row4col[rm1] = lane + 32; }
    unsigned bal0 = __ballot_sync(FULL, g_a0);
    unsigned bal1 = __ballot_sync(FULL, g_a1);
    const unsigned long long nmask = (n >= 64) ? ~0ull : ((1ull << n) - 1ull);
    unsigned long long free_rows =
        ~(((unsigned long long)bal1 << 32) | (unsigned long long)bal0) & nmask;
    __syncwarp();
#pragma unroll
    for (int k = 0; k < 8; k++) r4c[k] = row4col[lane + 32 * k];

    // ---- augmenting row reduction (JV): tighten duals, steal columns.
    // Per step: one pass computes lane-local (min, 2nd-min); after the first
    // redux (u1), the 2nd-min redux and the argmin-pack redux are independent
    // and overlap. Any row it cannot settle goes to exact Dijkstra below.
    unsigned long long dij = 0;
    {
        unsigned long long work = free_rows;
        int budget = 512;
        while (work) {
            int i = __ffsll((long long)work) - 1;
            work &= work - 1;
            bool active = true;
            while (active) {
                if (--budget < 0) { dij |= (1ull << i) | work; work = 0; break; }
                const float* crow = cost + i * CPAD;
                float rq[8];
#pragma unroll
                for (int k = 0; k < 8; k++) rq[k] = crow[lane + 32 * k] - vv[k];

                // lane-local (min m, 2nd-min s) via pairwise merge tree
                float lo01 = fminf(rq[0], rq[1]), hi01 = fmaxf(rq[0], rq[1]);
                float lo23 = fminf(rq[2], rq[3]), hi23 = fmaxf(rq[2], rq[3]);
                float lo45 = fminf(rq[4], rq[5]), hi45 = fmaxf(rq[4], rq[5]);
                float lo67 = fminf(rq[6], rq[7]), hi67 = fmaxf(rq[6], rq[7]);
                float loA = fminf(lo01, lo23);
                float sA  = fminf(fmaxf(lo01, lo23), fminf(hi01, hi23));
                float loB = fminf(lo45, lo67);
                float sB  = fminf(fmaxf(lo45, lo67), fminf(hi45, hi67));
                float m   = fminf(loA, loB);
                float s   = fminf(fmaxf(loA, loB), fminf(sA, sB));

                const unsigned km = f2k(m);
                const unsigned g1 = redux_min_u32(km);
                const float    u1 = k2f(g1);
                const bool     win = (km == g1);
                const unsigned nb  = __ballot_sync(FULL, win);

                // overlapped: global 2nd-min redux + argmin-pack redux
                const unsigned c2 = win ? f2k(s) : km;
                unsigned pk = 0xFFFFFFFFu;
#pragma unroll
                for (int k = 0; k < 8; k++) {
                    const unsigned c = ((unsigned)(lane + 32 * k) << 9)
                                     | (unsigned)(r4c[k] + 1);
                    pk = min(pk, (rq[k] == u1) ? c : 0xFFFFFFFFu);
                }
                const unsigned g2     = redux_min_u32(c2);
                const unsigned packed = redux_min_u32(pk);
                const float u2 = (__popc(nb) >= 2) ? u1 : k2f(g2);

                const int j1 = (int)(packed >> 9);
                const int k1 = (int)(packed & 511u) - 1;

                if (lane == 0) u[i] = u2;

                if (u1 < u2) {                // take j1 (steal if held)
                    if ((j1 & 31) == lane) { vv[j1 >> 5] -= (u2 - u1); r4c[j1 >> 5] = i; }
                    if (lane == 0) {
                        row4col[j1] = i; col4row[i] = j1;
                        if (k1 >= 0) col4row[k1] = -1;
                    }
                    if (k1 >= 0) i = k1;       // continue with displaced row
                    else         active = false;
                } else {                       // u1 == u2 (>=2 cols at u1)
                    if (k1 < 0) {              // j1 free: take it (slack 0)
                        if ((j1 & 31) == lane) r4c[j1 >> 5] = i;
                        if (lane == 0) { row4col[j1] = i; col4row[i] = j1; }
                        active = false;
                    } else {
                        // j2 = next col with rq == u2, excluding j1
                        unsigned pk2 = 0xFFFFFFFFu;
#pragma unroll
                        for (int k = 0; k < 8; k++) {
                            const int q = lane + 32 * k;
                            const unsigned c = ((unsigned)q << 9)
                                             | (unsigned)(r4c[k] + 1);
                            const bool ok = (q != j1) && (rq[k] == u2);
                            pk2 = min(pk2, ok ? c : 0xFFFFFFFFu);
                        }
                        const unsigned packed2 = redux_min_u32(pk2);
                        const int j2  = (int)(packed2 >> 9);
                        const int k2r = (int)(packed2 & 511u) - 1;
                        if (k2r < 0) {         // j2 free: take it (slack 0)
                            if ((j2 & 31) == lane) r4c[j2 >> 5] = i;
                            if (lane == 0) { row4col[j2] = i; col4row[i] = j2; }
                        } else {
                            dij |= 1ull << i;  // defer to Dijkstra
                        }
                        active = false;
                    }
                }
            }
        }
    }
    __syncwarp();

    // ---- exact Dijkstra augmentation for remaining rows
    while (dij) {
        const int cur_row = __ffsll((long long)dij) - 1;
        dij &= dij - 1;

        unsigned scanned = 0;          // bit k -> own column lane+32k in SC
        unsigned long long sr = 0;     // scanned-row set (uniform)
#pragma unroll
        for (int k = 0; k < 8; k++) sh[k] = FINF;

        int   i      = cur_row;
        float minval = 0.0f;
        int   sink;

        while (true) {
            sr |= 1ull << i;
            const float base = minval - u[i];
            const float* crow = cost + i * CPAD;

            float cand[8];
#pragma unroll
            for (int k = 0; k < 8; k++) {
                const int q = lane + 32 * k;
                const bool un = !((scanned >> k) & 1u);
                const float r = (base + crow[q]) - vv[k];
                if (un && r < sh[k]) { sh[k] = r; path[q] = i; }
                cand[k] = un ? sh[k] : FINF;
            }
            float m01 = fminf(cand[0], cand[1]), m23 = fminf(cand[2], cand[3]);
            float m45 = fminf(cand[4], cand[5]), m67 = fminf(cand[6], cand[7]);
            float bv  = fminf(fminf(m01, m23), fminf(m45, m67));
            const unsigned key = f2k(bv);

            unsigned pk = 0xFFFFFFFFu;
#pragma unroll
            for (int k = 0; k < 8; k++) {
                const unsigned c = ((unsigned)(lane + 32 * k) << 9)
                                 | (unsigned)(r4c[k] + 1);
                pk = min(pk, (cand[k] == bv) ? c : 0xFFFFFFFFu);
            }

            const unsigned gkey   = redux_min_u32(key);
            const unsigned pk2    = (key == gkey) ? pk : 0xFFFFFFFFu;
            const unsigned packed = redux_min_u32(pk2);
            minval = k2f(gkey);

            const int j  = (int)(packed >> 9);
            const int r4 = (int)(packed & 511u) - 1;
            if ((j & 31) == lane) scanned |= 1u << (j >> 5);
            if (r4 < 0) { sink = j; break; }
            i = r4;
        }

        // write back shortest for scanned columns (dual u update reads them)
#pragma unroll
        for (int k = 0; k < 8; k++)
            if ((scanned >> k) & 1u) shsh[lane + 32 * k] = sh[k];
        __syncwarp();

        // dual updates
#pragma unroll
        for (int h = 0; h < 2; h++) {
            const int r = lane + 32 * h;
            if (((sr >> r) & 1ull) && r != cur_row) {
                u[r] += minval - shsh[col4row[r]];
            }
        }
        if (lane == 0) u[cur_row] += minval;
#pragma unroll
        for (int k = 0; k < 8; k++) {
            if ((scanned >> k) & 1u) vv[k] -= minval - sh[k];
        }
        __syncwarp();

        // augment along alternating path (serial, lane 0)
        if (lane == 0) {
            int j = sink;
            while (true) {
                int ii = path[j];
                row4col[j] = ii;
                int t = col4row[ii];
                col4row[ii] = j;
                j = t;
                if (ii == cur_row) break;
            }
        }
        __syncwarp();
#pragma unroll
        for (int k = 0; k < 8; k++) r4c[k] = row4col[lane + 32 * k];
    }

    // ---- outputs
    float* out_ind  = out + (size_t)b * QQ;
    float* out_mask = out + (size_t)BB * QQ + (size_t)b * QQ;
#pragma unroll
    for (int k = 0; k < 8; k++) {
        const int q = lane + 32 * k;
        const int r = row4col[q];
        out_ind[q]  = (r >= 0) ? (float)r : 0.0f;
        out_mask[q] = (r >= 0) ? 1.0f : 0.0f;
    }
}

extern "C" void kernel_launch(void* const* d_in, const int* in_sizes, int n_in,
                              void* d_out, int out_size) {
    const float* gious = nullptr;
    const int*   nact  = nullptr;
    for (int i = 0; i < n_in; i++) {
        if (in_sizes[i] == BB * QQ * GG)      gious = (const float*)d_in[i];
        else if (in_sizes[i] == BB)           nact  = (const int*)d_in[i];
    }

    const size_t smem = (size_t)GG * CPAD * sizeof(float)   // cost
                      + (size_t)QQ * sizeof(float)          // shortest mirror
                      + (size_t)GG * sizeof(float)          // u
                      + (size_t)QQ * sizeof(int)            // path
                      + (size_t)QQ * sizeof(int)            // row4col
                      + (size_t)GG * sizeof(int)            // col4row
                      + (size_t)QQ * sizeof(int)            // claim
                      + (size_t)GG * sizeof(int);           // row argmin

    cudaFuncSetAttribute(matcher_lsa_kernel,
                         cudaFuncAttributeMaxDynamicSharedMemorySize, (int)smem);

    matcher_lsa_kernel<<<BB, 32, smem>>>(gious, nact, (float*)d_out);
}